// round 5
// baseline (speedup 1.0000x reference)
#include <cuda_runtime.h>
#include <cuda_bf16.h>
#include <stdint.h>

// BEVPool: out[b, :] = sum over points i with ranks_bev[i]==b of
//                      depth[ranks_depth[i]] * feat[ranks_feat[i], :]
// ranks_bev is SORTED -> each bin is a contiguous run of point indices.
// One 20-thread group per bin; each thread owns 4 channels (float4).
// Run boundaries found by binary search (9 lower_bounds per block of 8 bins).
// No atomics: each output element written exactly once.
//
// NOTE: JAX with default x64-disabled config downcasts the "int64" ranks to
// int32 — device buffers are int32.

#define C4 20            // 80 channels / 4 per float4
#define BINS_PER_BLOCK 8
#define THREADS (C4 * BINS_PER_BLOCK)  // 160

__global__ __launch_bounds__(THREADS)
void bevpool_kernel(const float* __restrict__ depth,
                    const float* __restrict__ feat,
                    const int* __restrict__ ranks_depth,
                    const int* __restrict__ ranks_feat,
                    const int* __restrict__ ranks_bev,
                    float* __restrict__ out,
                    int P, int total_bev)
{
    __shared__ int bound[BINS_PER_BLOCK + 1];

    const int b0 = blockIdx.x * BINS_PER_BLOCK;
    const int tid = threadIdx.x;

    // 9 lower_bound searches: first index i with ranks_bev[i] >= (b0 + tid)
    if (tid <= BINS_PER_BLOCK) {
        const int target = b0 + tid;
        int lo = 0, hi = P;
        while (lo < hi) {
            int mid = (lo + hi) >> 1;
            if (__ldg(&ranks_bev[mid]) < target) lo = mid + 1;
            else hi = mid;
        }
        bound[tid] = lo;
    }
    __syncthreads();

    const int y   = tid / C4;       // bin within block
    const int x   = tid % C4;       // float4 channel slot
    const int bin = b0 + y;
    if (bin >= total_bev) return;

    const int start = bound[y];
    const int end   = bound[y + 1];

    const float4* __restrict__ feat4 = (const float4*)feat;

    float4 acc = make_float4(0.f, 0.f, 0.f, 0.f);

    int i = start;
    // 4x unrolled main loop: batch index/depth/feat loads for MLP
    for (; i + 4 <= end; i += 4) {
        const int rd0 = __ldg(&ranks_depth[i + 0]);
        const int rd1 = __ldg(&ranks_depth[i + 1]);
        const int rd2 = __ldg(&ranks_depth[i + 2]);
        const int rd3 = __ldg(&ranks_depth[i + 3]);
        const int rf0 = __ldg(&ranks_feat[i + 0]);
        const int rf1 = __ldg(&ranks_feat[i + 1]);
        const int rf2 = __ldg(&ranks_feat[i + 2]);
        const int rf3 = __ldg(&ranks_feat[i + 3]);

        const float d0 = __ldg(&depth[rd0]);
        const float d1 = __ldg(&depth[rd1]);
        const float d2 = __ldg(&depth[rd2]);
        const float d3 = __ldg(&depth[rd3]);

        const float4 v0 = __ldg(&feat4[rf0 * C4 + x]);
        const float4 v1 = __ldg(&feat4[rf1 * C4 + x]);
        const float4 v2 = __ldg(&feat4[rf2 * C4 + x]);
        const float4 v3 = __ldg(&feat4[rf3 * C4 + x]);

        acc.x = fmaf(d0, v0.x, acc.x); acc.y = fmaf(d0, v0.y, acc.y);
        acc.z = fmaf(d0, v0.z, acc.z); acc.w = fmaf(d0, v0.w, acc.w);
        acc.x = fmaf(d1, v1.x, acc.x); acc.y = fmaf(d1, v1.y, acc.y);
        acc.z = fmaf(d1, v1.z, acc.z); acc.w = fmaf(d1, v1.w, acc.w);
        acc.x = fmaf(d2, v2.x, acc.x); acc.y = fmaf(d2, v2.y, acc.y);
        acc.z = fmaf(d2, v2.z, acc.z); acc.w = fmaf(d2, v2.w, acc.w);
        acc.x = fmaf(d3, v3.x, acc.x); acc.y = fmaf(d3, v3.y, acc.y);
        acc.z = fmaf(d3, v3.z, acc.z); acc.w = fmaf(d3, v3.w, acc.w);
    }
    // tail
    for (; i < end; i++) {
        const int rd = __ldg(&ranks_depth[i]);
        const int rf = __ldg(&ranks_feat[i]);
        const float d = __ldg(&depth[rd]);
        const float4 v = __ldg(&feat4[rf * C4 + x]);
        acc.x = fmaf(d, v.x, acc.x); acc.y = fmaf(d, v.y, acc.y);
        acc.z = fmaf(d, v.z, acc.z); acc.w = fmaf(d, v.w, acc.w);
    }

    ((float4*)out)[bin * C4 + x] = acc;
}

extern "C" void kernel_launch(void* const* d_in, const int* in_sizes, int n_in,
                              void* d_out, int out_size)
{
    const float* depth       = (const float*)d_in[0];
    const float* feat        = (const float*)d_in[1];
    const int*   ranks_depth = (const int*)d_in[2];
    const int*   ranks_feat  = (const int*)d_in[3];
    const int*   ranks_bev   = (const int*)d_in[4];
    // d_in[5] interval_starts, d_in[6] interval_lengths, d_in[7] total_bev: unused

    float* out = (float*)d_out;

    const int P         = in_sizes[2];       // 1,500,000
    const int total_bev = out_size / 80;     // 40,000

    const int grid = (total_bev + BINS_PER_BLOCK - 1) / BINS_PER_BLOCK;
    bevpool_kernel<<<grid, THREADS>>>(depth, feat, ranks_depth, ranks_feat,
                                      ranks_bev, out, P, total_bev);
}

// round 8
// speedup vs baseline: 1.0099x; 1.0099x over previous
#include <cuda_runtime.h>
#include <cuda_bf16.h>
#include <stdint.h>

// BEVPool: out[b, :] = sum_{i: ranks_bev[i]==b} depth[ranks_depth[i]] * feat[ranks_feat[i], :]
// ranks_bev sorted -> bins are contiguous runs; 8 consecutive bins per block
// cover ONE contiguous point range [bound[0], bound[8]).
//
// Two phases per chunk:
//   stage:   160 threads coalesce-load ranks + gather depth -> smem (once per point)
//   compute: 20-lane group per bin reads (rf, d) from smem (LDS broadcast),
//            issues only the feat float4 gathers to L1, accumulates in regs.
// No atomics; each output element written exactly once.
// NOTE: JAX x64-disabled => rank buffers are int32 on device.

#define C4 20                 // 80 channels / 4
#define BINS_PER_BLOCK 8
#define THREADS (C4 * BINS_PER_BLOCK)   // 160
#define CHUNK 512             // points staged per iteration

__global__ __launch_bounds__(THREADS)
void bevpool_kernel(const float* __restrict__ depth,
                    const float* __restrict__ feat,
                    const int* __restrict__ ranks_depth,
                    const int* __restrict__ ranks_feat,
                    const int* __restrict__ ranks_bev,
                    float* __restrict__ out,
                    int P, int total_bev)
{
    __shared__ int   bound[BINS_PER_BLOCK + 1];
    __shared__ int   s_rf[CHUNK];   // pre-scaled: rf * C4
    __shared__ float s_d[CHUNK];

    const int b0  = blockIdx.x * BINS_PER_BLOCK;
    const int tid = threadIdx.x;

    // lower_bound for 9 bin boundaries
    if (tid <= BINS_PER_BLOCK) {
        const int target = b0 + tid;
        int lo = 0, hi = P;
        while (lo < hi) {
            int mid = (lo + hi) >> 1;
            if (__ldg(&ranks_bev[mid]) < target) lo = mid + 1;
            else hi = mid;
        }
        bound[tid] = lo;
    }
    __syncthreads();

    const int blk_lo = bound[0];
    const int blk_hi = bound[BINS_PER_BLOCK];

    const int y   = tid / C4;     // bin within block
    const int x   = tid % C4;     // float4 slot
    const int start = bound[y];
    const int end   = bound[y + 1];

    const float4* __restrict__ feat4 = (const float4*)feat;

    float4 acc = make_float4(0.f, 0.f, 0.f, 0.f);

    for (int base = blk_lo; base < blk_hi; base += CHUNK) {
        const int n = min(CHUNK, blk_hi - base);

        // ---- stage phase: coalesced rank loads + depth gather -> smem ----
        for (int j = tid; j < n; j += THREADS) {
            const int idx = base + j;
            const int rd  = __ldg(&ranks_depth[idx]);
            const int rf  = __ldg(&ranks_feat[idx]);
            s_rf[j] = rf * C4;
            s_d[j]  = __ldg(&depth[rd]);
        }
        __syncthreads();

        // ---- compute phase: my bin's slice of this chunk ----
        const int lo = max(start, base) - base;
        const int hi = min(end, base + n) - base;

        int j = lo;
        for (; j + 4 <= hi; j += 4) {
            const int   r0 = s_rf[j + 0];
            const int   r1 = s_rf[j + 1];
            const int   r2 = s_rf[j + 2];
            const int   r3 = s_rf[j + 3];
            const float d0 = s_d[j + 0];
            const float d1 = s_d[j + 1];
            const float d2 = s_d[j + 2];
            const float d3 = s_d[j + 3];

            const float4 v0 = __ldg(&feat4[r0 + x]);
            const float4 v1 = __ldg(&feat4[r1 + x]);
            const float4 v2 = __ldg(&feat4[r2 + x]);
            const float4 v3 = __ldg(&feat4[r3 + x]);

            acc.x = fmaf(d0, v0.x, acc.x); acc.y = fmaf(d0, v0.y, acc.y);
            acc.z = fmaf(d0, v0.z, acc.z); acc.w = fmaf(d0, v0.w, acc.w);
            acc.x = fmaf(d1, v1.x, acc.x); acc.y = fmaf(d1, v1.y, acc.y);
            acc.z = fmaf(d1, v1.z, acc.z); acc.w = fmaf(d1, v1.w, acc.w);
            acc.x = fmaf(d2, v2.x, acc.x); acc.y = fmaf(d2, v2.y, acc.y);
            acc.z = fmaf(d2, v2.z, acc.z); acc.w = fmaf(d2, v2.w, acc.w);
            acc.x = fmaf(d3, v3.x, acc.x); acc.y = fmaf(d3, v3.y, acc.y);
            acc.z = fmaf(d3, v3.z, acc.z); acc.w = fmaf(d3, v3.w, acc.w);
        }
        for (; j < hi; j++) {
            const int   r = s_rf[j];
            const float d = s_d[j];
            const float4 v = __ldg(&feat4[r + x]);
            acc.x = fmaf(d, v.x, acc.x); acc.y = fmaf(d, v.y, acc.y);
            acc.z = fmaf(d, v.z, acc.z); acc.w = fmaf(d, v.w, acc.w);
        }
        __syncthreads();
    }

    const int bin = b0 + y;
    if (bin < total_bev)
        ((float4*)out)[bin * C4 + x] = acc;
}

extern "C" void kernel_launch(void* const* d_in, const int* in_sizes, int n_in,
                              void* d_out, int out_size)
{
    const float* depth       = (const float*)d_in[0];
    const float* feat        = (const float*)d_in[1];
    const int*   ranks_depth = (const int*)d_in[2];
    const int*   ranks_feat  = (const int*)d_in[3];
    const int*   ranks_bev   = (const int*)d_in[4];
    // d_in[5] interval_starts, d_in[6] interval_lengths, d_in[7] total_bev: unused

    float* out = (float*)d_out;

    const int P         = in_sizes[2];       // 1,500,000
    const int total_bev = out_size / 80;     // 40,000

    const int grid = (total_bev + BINS_PER_BLOCK - 1) / BINS_PER_BLOCK;
    bevpool_kernel<<<grid, THREADS>>>(depth, feat, ranks_depth, ranks_feat,
                                      ranks_bev, out, P, total_bev);
}

// round 9
// speedup vs baseline: 1.2289x; 1.2169x over previous
#include <cuda_runtime.h>
#include <cuda_bf16.h>
#include <stdint.h>

// BEVPool as a balanced segmented reduction over SORTED ranks_bev.
// Each 20-lane group owns a FIXED range of SUB consecutive points:
//   - stage phase: block coalesce-loads ranks_feat/ranks_bev and gathers depth
//     into smem (once per point)
//   - scan phase: group walks its range; run-length segments (same bev bin)
//     are accumulated in registers. Interior segments -> plain float4 store
//     (sole writer). Segments touching the range edge -> red.global.add.v4.f32
//     into zero-initialized output.
// Perfect load balance: every group has an identical trip count.
// NOTE: JAX x64-disabled => rank buffers are int32 on device.

#define C4 20                       // 80 channels / 4
#define GROUPS 8
#define THREADS (C4 * GROUPS)       // 160
#define SUB 96                      // points per group
#define CHUNK (GROUPS * SUB)        // 768 points per block

__device__ __forceinline__ void red_add_v4(float4* p, float4 v)
{
    asm volatile("red.global.add.v4.f32 [%0], {%1, %2, %3, %4};"
                 :: "l"(p), "f"(v.x), "f"(v.y), "f"(v.z), "f"(v.w)
                 : "memory");
}

__global__ void zero_out_kernel(float4* __restrict__ out4, int n4)
{
    int i = blockIdx.x * blockDim.x + threadIdx.x;
    if (i < n4) out4[i] = make_float4(0.f, 0.f, 0.f, 0.f);
}

__global__ __launch_bounds__(THREADS)
void bevpool_scan_kernel(const float* __restrict__ depth,
                         const float* __restrict__ feat,
                         const int* __restrict__ ranks_depth,
                         const int* __restrict__ ranks_feat,
                         const int* __restrict__ ranks_bev,
                         float* __restrict__ out,
                         int P)
{
    __shared__ int   s_rf[CHUNK];    // pre-scaled: rf * C4
    __shared__ float s_d[CHUNK];
    __shared__ int   s_bev[CHUNK];

    const int base = blockIdx.x * CHUNK;
    const int tid  = threadIdx.x;
    const int n    = min(CHUNK, P - base);
    if (n <= 0) return;

    // ---- stage: coalesced loads + depth gather -> smem ----
    #pragma unroll 2
    for (int j = tid; j < n; j += THREADS) {
        const int idx = base + j;
        const int rd  = __ldg(&ranks_depth[idx]);
        s_rf[j]  = __ldg(&ranks_feat[idx]) * C4;
        s_bev[j] = __ldg(&ranks_bev[idx]);
        s_d[j]   = __ldg(&depth[rd]);
    }
    __syncthreads();

    const int y = tid / C4;          // group id
    const int x = tid % C4;          // float4 channel slot

    const int lo = y * SUB;
    const int hi = min(lo + SUB, n);
    if (lo >= n) return;

    const float4* __restrict__ feat4 = (const float4*)feat;
    float4* __restrict__ out4        = (float4*)out;

    int    cur   = s_bev[lo];
    bool   first = true;             // current segment may extend left of range
    float4 acc   = make_float4(0.f, 0.f, 0.f, 0.f);

    int j = lo;
    for (; j + 4 <= hi; j += 4) {
        // batch-load (independent of segment logic) for MLP
        const int   r0 = s_rf[j + 0], r1 = s_rf[j + 1];
        const int   r2 = s_rf[j + 2], r3 = s_rf[j + 3];
        const float d0 = s_d[j + 0],  d1 = s_d[j + 1];
        const float d2 = s_d[j + 2],  d3 = s_d[j + 3];
        const int   b0 = s_bev[j + 0], b1 = s_bev[j + 1];
        const int   b2 = s_bev[j + 2], b3 = s_bev[j + 3];

        const float4 v0 = __ldg(&feat4[r0 + x]);
        const float4 v1 = __ldg(&feat4[r1 + x]);
        const float4 v2 = __ldg(&feat4[r2 + x]);
        const float4 v3 = __ldg(&feat4[r3 + x]);

        if (b0 != cur) {
            if (first) red_add_v4(&out4[cur * C4 + x], acc);
            else       out4[cur * C4 + x] = acc;
            first = false; acc = make_float4(0.f, 0.f, 0.f, 0.f); cur = b0;
        }
        acc.x = fmaf(d0, v0.x, acc.x); acc.y = fmaf(d0, v0.y, acc.y);
        acc.z = fmaf(d0, v0.z, acc.z); acc.w = fmaf(d0, v0.w, acc.w);

        if (b1 != cur) {
            if (first) red_add_v4(&out4[cur * C4 + x], acc);
            else       out4[cur * C4 + x] = acc;
            first = false; acc = make_float4(0.f, 0.f, 0.f, 0.f); cur = b1;
        }
        acc.x = fmaf(d1, v1.x, acc.x); acc.y = fmaf(d1, v1.y, acc.y);
        acc.z = fmaf(d1, v1.z, acc.z); acc.w = fmaf(d1, v1.w, acc.w);

        if (b2 != cur) {
            if (first) red_add_v4(&out4[cur * C4 + x], acc);
            else       out4[cur * C4 + x] = acc;
            first = false; acc = make_float4(0.f, 0.f, 0.f, 0.f); cur = b2;
        }
        acc.x = fmaf(d2, v2.x, acc.x); acc.y = fmaf(d2, v2.y, acc.y);
        acc.z = fmaf(d2, v2.z, acc.z); acc.w = fmaf(d2, v2.w, acc.w);

        if (b3 != cur) {
            if (first) red_add_v4(&out4[cur * C4 + x], acc);
            else       out4[cur * C4 + x] = acc;
            first = false; acc = make_float4(0.f, 0.f, 0.f, 0.f); cur = b3;
        }
        acc.x = fmaf(d3, v3.x, acc.x); acc.y = fmaf(d3, v3.y, acc.y);
        acc.z = fmaf(d3, v3.z, acc.z); acc.w = fmaf(d3, v3.w, acc.w);
    }
    for (; j < hi; j++) {
        const int   r = s_rf[j];
        const float d = s_d[j];
        const int   b = s_bev[j];
        const float4 v = __ldg(&feat4[r + x]);
        if (b != cur) {
            if (first) red_add_v4(&out4[cur * C4 + x], acc);
            else       out4[cur * C4 + x] = acc;
            first = false; acc = make_float4(0.f, 0.f, 0.f, 0.f); cur = b;
        }
        acc.x = fmaf(d, v.x, acc.x); acc.y = fmaf(d, v.y, acc.y);
        acc.z = fmaf(d, v.z, acc.z); acc.w = fmaf(d, v.w, acc.w);
    }

    // final segment may extend past the range edge -> always atomic
    red_add_v4(&out4[cur * C4 + x], acc);
}

extern "C" void kernel_launch(void* const* d_in, const int* in_sizes, int n_in,
                              void* d_out, int out_size)
{
    const float* depth       = (const float*)d_in[0];
    const float* feat        = (const float*)d_in[1];
    const int*   ranks_depth = (const int*)d_in[2];
    const int*   ranks_feat  = (const int*)d_in[3];
    const int*   ranks_bev   = (const int*)d_in[4];
    // d_in[5] interval_starts, d_in[6] interval_lengths, d_in[7] total_bev: unused

    float* out = (float*)d_out;

    const int P  = in_sizes[2];          // 1,500,000
    const int n4 = out_size / 4;         // float4 count (800,000)

    zero_out_kernel<<<(n4 + 255) / 256, 256>>>((float4*)out, n4);

    const int grid = (P + CHUNK - 1) / CHUNK;
    bevpool_scan_kernel<<<grid, THREADS>>>(depth, feat, ranks_depth,
                                           ranks_feat, ranks_bev, out, P);
}